// round 8
// baseline (speedup 1.0000x reference)
#include <cuda_runtime.h>

#define TDIM 512
#define NREC 256
#define NIN 10
#define NOUT 3
#define BATCH 1024
#define ROWS 8
#define NB (BATCH/ROWS)     // 128 blocks
#define NT 256              // 8 warps: 4 col-pair warps x 2 j-halves
#define HALF 128
#define JS 128              // j-half size
#define WPAD 132            // padded W row: conflict-free LDS.128
#define NSTREAM (JS/4)      // 32 packs of 4 j streamed from L2
#define PD 4                // LDG prefetch distance (iterations)

typedef unsigned long long u64;

__device__ ulonglong2 g_Wst[NSTREAM * NREC];   // [kb][c]: W_rec[c][128+4kb..+3], 128 KB
__device__ float g_l2p[NB];
__device__ unsigned int g_ctr;

static __device__ __forceinline__ u64 pk(float a, float b){
    u64 r; asm("mov.b64 %0,{%1,%2};":"=l"(r):"f"(a),"f"(b)); return r;
}
static __device__ __forceinline__ u64 fm2(u64 a, u64 b, u64 c){
    u64 d; asm("fma.rn.f32x2 %0,%1,%2,%3;":"=l"(d):"l"(a),"l"(b),"l"(c)); return d;
}
static __device__ __forceinline__ float2 up(u64 v){
    float2 f; asm("mov.b64 {%0,%1},%2;":"=f"(f.x),"=f"(f.y):"l"(v)); return f;
}

__global__ void prep_kernel(const float* __restrict__ W){
    int c = threadIdx.x;   // 256 threads
    const ulonglong2* row = (const ulonglong2*)(W + c * NREC);
    #pragma unroll
    for (int k = 0; k < NSTREAM; k++)
        g_Wst[k * NREC + c] = row[JS/4 + k];
}

__global__ __launch_bounds__(NT, 1)
void rnn_kernel(const float* __restrict__ x,
                const float* __restrict__ noise,
                const float* __restrict__ W_in,
                const float* __restrict__ W_rec,
                const float* __restrict__ W_out,
                const float* __restrict__ b_out,
                const float* __restrict__ bias,
                float* __restrict__ out, int out_size)
{
    extern __shared__ float sm[];
    float* Wsm = sm;                          // [256 c][WPAD] j<128, 135 KB
    float* rT  = Wsm + NREC * WPAD;           // [2][ROWS][NREC] double-buffered
    float* ps  = rT + 2 * ROWS * NREC;        // [ROWS][NREC] upper-half partials, 8 KB
    float* WoS = ps + ROWS * NREC;            // [3][256]
    float* xb  = WoS + NOUT * NREC;           // [2][ROWS][12]

    const int tid  = threadIdx.x;
    const int b0   = blockIdx.x * ROWS;
    const int wid  = tid >> 5, lane = tid & 31;
    const int pair = wid & 3;                 // col-pair group
    const bool lowerH = (wid < 4);            // j in [0,128) from SMEM
    const int c0 = pair * 64 + lane;
    const int c1 = c0 + 32;

    // ---- init SMEM ----
    for (int idx = tid; idx < NREC * JS; idx += NT){
        int cc = idx >> 7, j = idx & (JS - 1);
        Wsm[cc * WPAD + j] = W_rec[cc * NREC + j];
    }
    for (int idx = tid; idx < 2 * ROWS * NREC; idx += NT) rT[idx] = 0.f;
    for (int idx = tid; idx < NOUT * NREC; idx += NT) WoS[idx] = W_out[idx];
    if (tid < ROWS * NIN){
        int i = tid / NIN, k = tid % NIN;
        xb[i * 12 + k] = x[(size_t)(b0 + i) * TDIM * NIN + k];   // t=0 into buf 0
    }

    // lower half owns u (bias + noise + x W_in) and the state update
    float win0[NIN], win1[NIN];
    float bs0 = 0.f, bs1 = 0.f;
    float r0[ROWS], r1[ROWS], nz0[ROWS], nz1[ROWS];
    if (lowerH){
        #pragma unroll
        for (int k = 0; k < NIN; k++){
            win0[k] = W_in[c0 * NIN + k];
            win1[k] = W_in[c1 * NIN + k];
        }
        bs0 = bias[c0]; bs1 = bias[c1];
        #pragma unroll
        for (int i = 0; i < ROWS; i++){
            size_t nb = (size_t)(b0 + i) * TDIM * NREC;
            nz0[i] = noise[nb + c0];
            nz1[i] = noise[nb + c1];
            r0[i] = 0.f; r1[i] = 0.f;
        }
    }
    const float bo0 = b_out[0], bo1 = b_out[1], bo2 = b_out[2];

    double l2d = 0.0;
    __syncthreads();

    const ulonglong2* __restrict__ wA0 = (const ulonglong2*)(Wsm + c0 * WPAD);
    const ulonglong2* __restrict__ wA1 = (const ulonglong2*)(Wsm + c1 * WPAD);
    const ulonglong2* __restrict__ gw  = g_Wst;

    for (int ts = 0; ts < TDIM; ts++){
        const int cur = ts & 1, nxt = cur ^ 1;
        const float* rTc = rT + cur * ROWS * NREC;
        float*       rTn = rT + nxt * ROWS * NREC;
        const float* xbc = xb + cur * 96;
        float*       xbn = xb + nxt * 96;
        const ulonglong2* __restrict__ rr = (const ulonglong2*)rTc;  // [ROWS][64]

        u64 a0[ROWS], a1[ROWS];
        #pragma unroll
        for (int i = 0; i < ROWS; i++){ a0[i] = pk(0.f, 0.f); a1[i] = pk(0.f, 0.f); }

        if (lowerH){
            // next-step noise prefetch first (DRAM latency hides under GEMM)
            float pn0[ROWS], pn1[ROWS];
            int tn = (ts + 1 < TDIM) ? ts + 1 : ts;
            #pragma unroll
            for (int i = 0; i < ROWS; i++){
                size_t nb = ((size_t)(b0 + i) * TDIM + tn) * NREC;
                pn0[i] = noise[nb + c0];
                pn1[i] = noise[nb + c1];
            }

            // GEMM: j in [0,128), weights from SMEM
            #pragma unroll 4
            for (int jb = 0; jb < JS/4; jb++){
                ulonglong2 w0 = wA0[jb];
                ulonglong2 w1 = wA1[jb];
                #pragma unroll
                for (int i = 0; i < ROWS; i++){
                    ulonglong2 rv = rr[i * 64 + jb];
                    a0[i] = fm2(rv.x, w0.x, a0[i]);
                    a0[i] = fm2(rv.y, w0.y, a0[i]);
                    a1[i] = fm2(rv.x, w1.x, a1[i]);
                    a1[i] = fm2(rv.y, w1.y, a1[i]);
                }
            }

            // u = bias + noise + x @ W_in^T (overlaps other half's exchange)
            float u0[ROWS], u1[ROWS];
            #pragma unroll
            for (int i = 0; i < ROWS; i++){ u0[i] = bs0 + nz0[i]; u1[i] = bs1 + nz1[i]; }
            #pragma unroll
            for (int i = 0; i < ROWS; i++){
                #pragma unroll
                for (int k = 0; k < NIN; k++){
                    float xv = xbc[i * 12 + k];
                    u0[i] = fmaf(xv, win0[k], u0[i]);
                    u1[i] = fmaf(xv, win1[k], u1[i]);
                }
            }
            #pragma unroll
            for (int i = 0; i < ROWS; i++){ nz0[i] = pn0[i]; nz1[i] = pn1[i]; }

            __syncthreads();   // upper partials (ps) published

            // v = low + high + u ; r update ; publish rTn
            float ssum = 0.f;
            #pragma unroll
            for (int i = 0; i < ROWS; i++){
                float2 v0 = up(a0[i]);
                float2 v1 = up(a1[i]);
                float vv0 = (v0.x + v0.y) + ps[i * NREC + c0] + u0[i];
                float vv1 = (v1.x + v1.y) + ps[i * NREC + c1] + u1[i];
                r0[i] = 0.8f * r0[i] + 0.2f * fmaxf(vv0, 0.f);
                r1[i] = 0.8f * r1[i] + 0.2f * fmaxf(vv1, 0.f);
                rTn[i * NREC + c0] = r0[i];
                rTn[i * NREC + c1] = r1[i];
                ssum = fmaf(r0[i], r0[i], ssum);
                ssum = fmaf(r1[i], r1[i], ssum);
            }
            l2d += (double)ssum;
        } else {
            // GEMM: j in [128,256), weights via LDG.128 with distance-PD pipeline
            ulonglong2 wb0[PD], wb1[PD];
            #pragma unroll
            for (int q = 0; q < PD; q++){
                wb0[q] = gw[q * NREC + c0];
                wb1[q] = gw[q * NREC + c1];
            }
            #pragma unroll 4
            for (int kb = 0; kb < NSTREAM; kb++){
                ulonglong2 w0 = wb0[kb & (PD-1)];
                ulonglong2 w1 = wb1[kb & (PD-1)];
                int kn = kb + PD;
                if (kn < NSTREAM){
                    wb0[kb & (PD-1)] = gw[kn * NREC + c0];
                    wb1[kb & (PD-1)] = gw[kn * NREC + c1];
                }
                #pragma unroll
                for (int i = 0; i < ROWS; i++){
                    ulonglong2 rv = rr[i * 64 + JS/4 + kb];
                    a0[i] = fm2(rv.x, w0.x, a0[i]);
                    a0[i] = fm2(rv.y, w0.y, a0[i]);
                    a1[i] = fm2(rv.x, w1.x, a1[i]);
                    a1[i] = fm2(rv.y, w1.y, a1[i]);
                }
            }
            // reduce + publish partials (coalesced STS.32: lanes -> consecutive cols)
            #pragma unroll
            for (int i = 0; i < ROWS; i++){
                float2 v0 = up(a0[i]);
                float2 v1 = up(a1[i]);
                ps[i * NREC + c0] = v0.x + v0.y;
                ps[i * NREC + c1] = v1.x + v1.y;
            }
            // next x tile prefetch (upper threads: tid-128 in [0,128))
            int tu = tid - HALF;
            if (tu < ROWS * NIN){
                int i = tu / NIN, k = tu % NIN;
                int tn = (ts + 1 < TDIM) ? ts + 1 : ts;
                xbn[i * 12 + k] = x[((size_t)(b0 + i) * TDIM + tn) * NIN + k];
            }

            __syncthreads();   // ps published (pairs with lower's barrier)
        }

        __syncthreads();   // rTn complete

        // z = r_new @ W_out^T + b_out ; warp w -> batch row w
        {
            float z0 = 0.f, z1 = 0.f, z2 = 0.f;
            #pragma unroll
            for (int q = 0; q < NREC/32; q++){
                int jj = lane + 32 * q;
                float ra = rTn[wid * NREC + jj];
                z0 = fmaf(ra, WoS[jj],          z0);
                z1 = fmaf(ra, WoS[NREC + jj],   z1);
                z2 = fmaf(ra, WoS[2*NREC + jj], z2);
            }
            #pragma unroll
            for (int off = 16; off; off >>= 1){
                z0 += __shfl_down_sync(~0u, z0, off);
                z1 += __shfl_down_sync(~0u, z1, off);
                z2 += __shfl_down_sync(~0u, z2, off);
            }
            if (lane == 0){
                size_t ob = ((size_t)(b0 + wid) * TDIM + ts) * NOUT;
                out[ob+0] = z0 + bo0; out[ob+1] = z1 + bo1; out[ob+2] = z2 + bo2;
            }
        }
    }

    // ---- deterministic l2 reduction, last-block finalization ----
    __syncthreads();
    double* dd = (double*)sm;
    dd[tid] = l2d;
    __syncthreads();
    if (tid == 0){
        double s = 0.0;
        #pragma unroll 8
        for (int i = 0; i < NT; i++) s += dd[i];
        g_l2p[blockIdx.x] = (float)s;
        __threadfence();
        unsigned int old = atomicInc(&g_ctr, NB - 1);
        if (old == NB - 1){
            __threadfence();
            double tot = 0.0;
            for (int i = 0; i < NB; i++) tot += (double)g_l2p[i];
            out[out_size - 1] = (float)(tot / ((double)TDIM * BATCH * NREC));
        }
    }
}

extern "C" void kernel_launch(void* const* d_in, const int* in_sizes, int n_in,
                              void* d_out, int out_size)
{
    const float* x     = (const float*)d_in[0];
    const float* noise = (const float*)d_in[1];
    const float* W_in  = (const float*)d_in[2];
    const float* W_rec = (const float*)d_in[3];
    const float* W_out = (const float*)d_in[4];
    const float* b_out = (const float*)d_in[5];
    const float* bias  = (const float*)d_in[6];
    float* out = (float*)d_out;

    size_t smem = (size_t)(NREC*WPAD + 2*ROWS*NREC + ROWS*NREC + NOUT*NREC + 2*96) * sizeof(float);
    cudaFuncSetAttribute(rnn_kernel, cudaFuncAttributeMaxDynamicSharedMemorySize, (int)smem);

    prep_kernel<<<1, 256>>>(W_rec);
    rnn_kernel<<<NB, NT, smem>>>(x, noise, W_in, W_rec, W_out, b_out, bias, out, out_size);
}

// round 9
// speedup vs baseline: 1.0230x; 1.0230x over previous
#include <cuda_runtime.h>

#define TDIM 512
#define NREC 256
#define NIN 10
#define NOUT 3
#define BATCH 1024
#define ROWS 8
#define NB (BATCH/ROWS)     // 128 blocks
#define NT 512              // 16 warps, 4/SMSP; 4 j-quarters x 128 col-pair threads
#define QT 128              // threads per quarter
#define JS 128              // j rows cached in SMEM (quarters 0,1)
#define WPAD 132            // padded W row: conflict-free LDS.128
#define NSTREAM (JS/4)      // 32 packs of 4 j streamed from L2 (quarters 2,3)
#define PD 4                // LDG prefetch distance

typedef unsigned long long u64;

__device__ ulonglong2 g_Wst[NSTREAM * NREC];   // [kb][c]: W_rec[c][128+4kb..+3], 128 KB
__device__ float g_l2p[NB];
__device__ unsigned int g_ctr;

static __device__ __forceinline__ u64 pk(float a, float b){
    u64 r; asm("mov.b64 %0,{%1,%2};":"=l"(r):"f"(a),"f"(b)); return r;
}
static __device__ __forceinline__ u64 fm2(u64 a, u64 b, u64 c){
    u64 d; asm("fma.rn.f32x2 %0,%1,%2,%3;":"=l"(d):"l"(a),"l"(b),"l"(c)); return d;
}
static __device__ __forceinline__ float2 up(u64 v){
    float2 f; asm("mov.b64 {%0,%1},%2;":"=f"(f.x),"=f"(f.y):"l"(v)); return f;
}

__global__ void prep_kernel(const float* __restrict__ W){
    int c = threadIdx.x;   // 256 threads
    const ulonglong2* row = (const ulonglong2*)(W + c * NREC);
    #pragma unroll
    for (int k = 0; k < NSTREAM; k++)
        g_Wst[k * NREC + c] = row[JS/4 + k];
}

__global__ __launch_bounds__(NT, 1)
void rnn_kernel(const float* __restrict__ x,
                const float* __restrict__ noise,
                const float* __restrict__ W_in,
                const float* __restrict__ W_rec,
                const float* __restrict__ W_out,
                const float* __restrict__ b_out,
                const float* __restrict__ bias,
                float* __restrict__ out, int out_size)
{
    extern __shared__ float sm[];
    float* Wsm = sm;                          // [256 c][WPAD] j<128, 135 KB
    float* rT  = Wsm + NREC * WPAD;           // [ROWS][NREC] single buffer (2 barriers make it safe)
    float* ps  = rT + ROWS * NREC;            // [3][ROWS][NREC] partials from q1..q3, 24 KB
    float* us  = ps + 3 * ROWS * NREC;        // [ROWS][NREC] u drive from q1, 8 KB
    float* WoS = us + ROWS * NREC;            // [3][256]
    float* xb  = WoS + NOUT * NREC;           // [2][ROWS][12]

    const int tid  = threadIdx.x;
    const int b0   = blockIdx.x * ROWS;
    const int wid  = tid >> 5, lane = tid & 31;
    const int q    = tid >> 7;                // j-quarter 0..3
    const int t    = tid & (QT - 1);
    const int c0   = t;
    const int c1   = t + QT;

    // ---- init SMEM ----
    for (int idx = tid; idx < NREC * JS; idx += NT){
        int cc = idx >> 7, j = idx & (JS - 1);
        Wsm[cc * WPAD + j] = W_rec[cc * NREC + j];
    }
    for (int idx = tid; idx < ROWS * NREC; idx += NT) rT[idx] = 0.f;
    for (int idx = tid; idx < NOUT * NREC; idx += NT) WoS[idx] = W_out[idx];
    if (tid < ROWS * NIN){
        int i = tid / NIN, k = tid % NIN;
        xb[i * 12 + k] = x[(size_t)(b0 + i) * TDIM * NIN + k];   // t=0 into buf 0
    }

    // q1 owns the drive u ; q0 owns the state update
    float win0[NIN], win1[NIN];
    float bs0 = 0.f, bs1 = 0.f;
    if (q == 1){
        #pragma unroll
        for (int k = 0; k < NIN; k++){
            win0[k] = W_in[c0 * NIN + k];
            win1[k] = W_in[c1 * NIN + k];
        }
        bs0 = bias[c0]; bs1 = bias[c1];
    }
    float r0[ROWS], r1[ROWS];
    #pragma unroll
    for (int i = 0; i < ROWS; i++){ r0[i] = 0.f; r1[i] = 0.f; }
    const float bo0 = b_out[0], bo1 = b_out[1], bo2 = b_out[2];

    double l2d = 0.0;
    __syncthreads();

    const ulonglong2* __restrict__ wA0 = (const ulonglong2*)(Wsm + c0 * WPAD);
    const ulonglong2* __restrict__ wA1 = (const ulonglong2*)(Wsm + c1 * WPAD);
    const ulonglong2* __restrict__ gw  = g_Wst;
    const ulonglong2* __restrict__ rr  = (const ulonglong2*)rT;   // [ROWS][64]

    for (int ts = 0; ts < TDIM; ts++){
        const int cur = ts & 1, nxt = cur ^ 1;
        const float* xbc = xb + cur * 96;
        float*       xbn = xb + nxt * 96;

        u64 a0[ROWS], a1[ROWS];
        #pragma unroll
        for (int i = 0; i < ROWS; i++){ a0[i] = pk(0.f, 0.f); a1[i] = pk(0.f, 0.f); }

        if (q < 2){
            // q1: issue this-step noise loads FIRST (consumed after GEMM tail)
            float nz0[ROWS], nz1[ROWS];
            if (q == 1){
                #pragma unroll
                for (int i = 0; i < ROWS; i++){
                    size_t nb = ((size_t)(b0 + i) * TDIM + ts) * NREC;
                    nz0[i] = noise[nb + c0];
                    nz1[i] = noise[nb + c1];
                }
            }
            // GEMM quarter from SMEM: jb in [16q, 16q+16)
            const int jb0 = q * 16;
            #pragma unroll 4
            for (int jj = 0; jj < 16; jj++){
                int jb = jb0 + jj;
                ulonglong2 w0 = wA0[jb];
                ulonglong2 w1 = wA1[jb];
                #pragma unroll
                for (int i = 0; i < ROWS; i++){
                    ulonglong2 rv = rr[i * 64 + jb];
                    a0[i] = fm2(rv.x, w0.x, a0[i]);
                    a0[i] = fm2(rv.y, w0.y, a0[i]);
                    a1[i] = fm2(rv.x, w1.x, a1[i]);
                    a1[i] = fm2(rv.y, w1.y, a1[i]);
                }
            }
            if (q == 1){
                // u = bias + noise + x @ W_in^T -> smem
                #pragma unroll
                for (int i = 0; i < ROWS; i++){
                    float u0 = bs0 + nz0[i], u1 = bs1 + nz1[i];
                    #pragma unroll
                    for (int k = 0; k < NIN; k++){
                        float xv = xbc[i * 12 + k];
                        u0 = fmaf(xv, win0[k], u0);
                        u1 = fmaf(xv, win1[k], u1);
                    }
                    us[i * NREC + c0] = u0;
                    us[i * NREC + c1] = u1;
                }
                // publish q1 partials
                #pragma unroll
                for (int i = 0; i < ROWS; i++){
                    float2 v0 = up(a0[i]);
                    float2 v1 = up(a1[i]);
                    ps[i * NREC + c0] = v0.x + v0.y;
                    ps[i * NREC + c1] = v1.x + v1.y;
                }
            }
        } else {
            // GEMM quarter from L2 via LDG.128, distance-PD pipeline: kb in [16(q-2), +16)
            const int kb0 = (q - 2) * 16;
            ulonglong2 wb0[PD], wb1[PD];
            #pragma unroll
            for (int p = 0; p < PD; p++){
                wb0[p] = gw[(kb0 + p) * NREC + c0];
                wb1[p] = gw[(kb0 + p) * NREC + c1];
            }
            #pragma unroll 4
            for (int jj = 0; jj < 16; jj++){
                ulonglong2 w0 = wb0[jj & (PD-1)];
                ulonglong2 w1 = wb1[jj & (PD-1)];
                if (jj + PD < 16){
                    wb0[jj & (PD-1)] = gw[(kb0 + jj + PD) * NREC + c0];
                    wb1[jj & (PD-1)] = gw[(kb0 + jj + PD) * NREC + c1];
                }
                #pragma unroll
                for (int i = 0; i < ROWS; i++){
                    ulonglong2 rv = rr[i * 64 + 32 + kb0 + jj];
                    a0[i] = fm2(rv.x, w0.x, a0[i]);
                    a0[i] = fm2(rv.y, w0.y, a0[i]);
                    a1[i] = fm2(rv.x, w1.x, a1[i]);
                    a1[i] = fm2(rv.y, w1.y, a1[i]);
                }
            }
            // publish partials (slots 1,2 for q2,q3)
            float* psq = ps + (q - 1) * ROWS * NREC;
            #pragma unroll
            for (int i = 0; i < ROWS; i++){
                float2 v0 = up(a0[i]);
                float2 v1 = up(a1[i]);
                psq[i * NREC + c0] = v0.x + v0.y;
                psq[i * NREC + c1] = v1.x + v1.y;
            }
            // q2 prefetches next x tile
            if (q == 2 && t < ROWS * NIN){
                int i = t / NIN, k = t % NIN;
                int tn = (ts + 1 < TDIM) ? ts + 1 : ts;
                xbn[i * 12 + k] = x[((size_t)(b0 + i) * TDIM + tn) * NIN + k];
            }
        }

        __syncthreads();   // barrier 1: ps/us published; all GEMM reads of rT done

        if (q == 0){
            // combine: v = my quarter + 3 partials + u ; update state in place
            float ssum = 0.f;
            #pragma unroll
            for (int i = 0; i < ROWS; i++){
                float2 v0 = up(a0[i]);
                float2 v1 = up(a1[i]);
                int o = i * NREC;
                float vv0 = (v0.x + v0.y) + ps[o + c0] + ps[ROWS*NREC + o + c0]
                          + ps[2*ROWS*NREC + o + c0] + us[o + c0];
                float vv1 = (v1.x + v1.y) + ps[o + c1] + ps[ROWS*NREC + o + c1]
                          + ps[2*ROWS*NREC + o + c1] + us[o + c1];
                r0[i] = 0.8f * r0[i] + 0.2f * fmaxf(vv0, 0.f);
                r1[i] = 0.8f * r1[i] + 0.2f * fmaxf(vv1, 0.f);
                rT[o + c0] = r0[i];
                rT[o + c1] = r1[i];
                ssum = fmaf(r0[i], r0[i], ssum);
                ssum = fmaf(r1[i], r1[i], ssum);
            }
            l2d += (double)ssum;
        }

        __syncthreads();   // barrier 2: rT updated

        // z = r_new @ W_out^T + b_out ; warps 0-7 -> batch rows 0-7
        if (wid < ROWS){
            float z0 = 0.f, z1 = 0.f, z2 = 0.f;
            #pragma unroll
            for (int qq = 0; qq < NREC/32; qq++){
                int jj = lane + 32 * qq;
                float ra = rT[wid * NREC + jj];
                z0 = fmaf(ra, WoS[jj],          z0);
                z1 = fmaf(ra, WoS[NREC + jj],   z1);
                z2 = fmaf(ra, WoS[2*NREC + jj], z2);
            }
            #pragma unroll
            for (int off = 16; off; off >>= 1){
                z0 += __shfl_down_sync(~0u, z0, off);
                z1 += __shfl_down_sync(~0u, z1, off);
                z2 += __shfl_down_sync(~0u, z2, off);
            }
            if (lane == 0){
                size_t ob = ((size_t)(b0 + wid) * TDIM + ts) * NOUT;
                out[ob+0] = z0 + bo0; out[ob+1] = z1 + bo1; out[ob+2] = z2 + bo2;
            }
        }
    }

    // ---- deterministic l2 reduction, last-block finalization ----
    __syncthreads();
    double* dd = (double*)sm;
    dd[tid] = l2d;
    __syncthreads();
    if (tid == 0){
        double s = 0.0;
        #pragma unroll 8
        for (int i = 0; i < QT; i++) s += dd[i];   // only q0 threads contributed
        g_l2p[blockIdx.x] = (float)s;
        __threadfence();
        unsigned int old = atomicInc(&g_ctr, NB - 1);
        if (old == NB - 1){
            __threadfence();
            double tot = 0.0;
            for (int i = 0; i < NB; i++) tot += (double)g_l2p[i];
            out[out_size - 1] = (float)(tot / ((double)TDIM * BATCH * NREC));
        }
    }
}

extern "C" void kernel_launch(void* const* d_in, const int* in_sizes, int n_in,
                              void* d_out, int out_size)
{
    const float* x     = (const float*)d_in[0];
    const float* noise = (const float*)d_in[1];
    const float* W_in  = (const float*)d_in[2];
    const float* W_rec = (const float*)d_in[3];
    const float* W_out = (const float*)d_in[4];
    const float* b_out = (const float*)d_in[5];
    const float* bias  = (const float*)d_in[6];
    float* out = (float*)d_out;

    size_t smem = (size_t)(NREC*WPAD + ROWS*NREC + 3*ROWS*NREC + ROWS*NREC
                           + NOUT*NREC + 2*96) * sizeof(float);
    cudaFuncSetAttribute(rnn_kernel, cudaFuncAttributeMaxDynamicSharedMemorySize, (int)smem);

    prep_kernel<<<1, 256>>>(W_rec);
    rnn_kernel<<<NB, NT, smem>>>(x, noise, W_in, W_rec, W_out, b_out, bias, out, out_size);
}